// round 12
// baseline (speedup 1.0000x reference)
#include <cuda_runtime.h>
#include <cuda_fp16.h>
#include <math.h>
#include <stdint.h>

#define BATCH 16
#define CCH   256
#define HW    4096
#define NPOS  (BATCH*HW)
#define QDIM  64
#define SD    512
#define NANG  18

typedef unsigned short ushort_t;

// ---------------- scratch globals ----------------
__device__ float g_cth[BATCH * NANG];
__device__ float g_sth[BATCH * NANG];
__device__ float g_Uri[BATCH * 128 * 64];        // rows 2a=Re, 2a+1=Im of U
__device__ float g_bf[BATCH * 128];              // Ũ @ b1
// W1f fragment-linear fp16 hi/lo: per batch 8 mt x 16 ks x 32 lane x 8 ushorts
__device__ __align__(16) ushort_t g_A1h[BATCH][32768];
__device__ __align__(16) ushort_t g_A1l[BATCH][32768];
// W2 fragment-linear: 16 mt x 4 ks x 32 x 8
__device__ __align__(16) ushort_t g_A2h[16384];
__device__ __align__(16) ushort_t g_A2l[16384];

// ---------------- mma helper ----------------
__device__ __forceinline__ void mma16816(float* c, uint32_t a0, uint32_t a1,
                                         uint32_t a2, uint32_t a3,
                                         uint32_t b0, uint32_t b1) {
  asm volatile(
      "mma.sync.aligned.m16n8k16.row.col.f32.f16.f16.f32 "
      "{%0,%1,%2,%3}, {%4,%5,%6,%7}, {%8,%9}, {%0,%1,%2,%3};"
      : "+f"(c[0]), "+f"(c[1]), "+f"(c[2]), "+f"(c[3])
      : "r"(a0), "r"(a1), "r"(a2), "r"(a3), "r"(b0), "r"(b1));
}

__device__ __forceinline__ void split16(float v, ushort_t& h, ushort_t& l) {
  __half hh = __float2half_rn(v);
  float lo = v - __half2float(hh);
  h = __half_as_ushort(hh);
  l = __half_as_ushort(__float2half_rn(lo));
}

// fragment-linear ushort index for A operand (m16n8k16 row-major A)
__device__ __forceinline__ int frag_idx(int r, int k, int KS) {
  int mt = r >> 4, rr = r & 15;
  int gID = rr & 7, sm = rr >> 3;
  int ks = k >> 4, kin = k & 15;
  int sk = kin >> 3, tg = (kin & 7) >> 1, hf = kin & 1;
  return (((mt * KS + ks) * 32 + gID * 4 + tg) * 4 + (sm + 2 * sk)) * 2 + hf;
}

// ---------------------------------------------------------------------------
// Kernel 1: per-batch angles
// ---------------------------------------------------------------------------
__global__ __launch_bounds__(512) void k_angles(
    const float* __restrict__ style, const float* __restrict__ smw,
    const float* __restrict__ smb, const float* __restrict__ wts) {
  int b = blockIdx.x, t = threadIdx.x, w = t >> 5, lane = t & 31;
  float sv = style[b * SD + t];
  __shared__ float red[NANG][16];
#pragma unroll
  for (int o = 0; o < NANG; o++) {
    float p = smw[o * SD + t] * sv;
#pragma unroll
    for (int off = 16; off > 0; off >>= 1) p += __shfl_xor_sync(0xffffffffu, p, off);
    if (lane == 0) red[o][w] = p;
  }
  __syncthreads();
  if (t < NANG) {
    float s = 0.f;
#pragma unroll
    for (int k = 0; k < 16; k++) s += red[t][k];
    float tp = wts[t] + smb[t] + s;
    g_cth[b * NANG + t] = cosf(0.5f * tp);
    g_sth[b * NANG + t] = sinf(0.5f * tp);
  }
}

// ---------------------------------------------------------------------------
// circuit helpers
// ---------------------------------------------------------------------------
__device__ __forceinline__ void rx_sh(float& r0, float& i0, float& r1, float& i1,
                                      float c, float s, int L) {
  float pr0 = __shfl_xor_sync(0xffffffffu, r0, L), pi0 = __shfl_xor_sync(0xffffffffu, i0, L);
  float pr1 = __shfl_xor_sync(0xffffffffu, r1, L), pi1 = __shfl_xor_sync(0xffffffffu, i1, L);
  r0 = fmaf(s, pi0, c * r0);  i0 = fmaf(-s, pr0, c * i0);
  r1 = fmaf(s, pi1, c * r1);  i1 = fmaf(-s, pr1, c * i1);
}
__device__ __forceinline__ void rx_loc(float& r0, float& i0, float& r1, float& i1,
                                       float c, float s) {
  float nr0 = fmaf(s, i1, c * r0), ni0 = fmaf(-s, r1, c * i0);
  float nr1 = fmaf(s, i0, c * r1), ni1 = fmaf(-s, r0, c * i1);
  r0 = nr0; i0 = ni0; r1 = nr1; i1 = ni1;
}
__device__ __forceinline__ void ry_sh(float& r0, float& i0, float& r1, float& i1,
                                      float c, float s, int L, int lane) {
  float t = (lane & L) ? s : -s;
  float pr0 = __shfl_xor_sync(0xffffffffu, r0, L), pi0 = __shfl_xor_sync(0xffffffffu, i0, L);
  float pr1 = __shfl_xor_sync(0xffffffffu, r1, L), pi1 = __shfl_xor_sync(0xffffffffu, i1, L);
  r0 = fmaf(t, pr0, c * r0);  i0 = fmaf(t, pi0, c * i0);
  r1 = fmaf(t, pr1, c * r1);  i1 = fmaf(t, pi1, c * i1);
}
__device__ __forceinline__ void ry_loc(float& r0, float& i0, float& r1, float& i1,
                                       float c, float s) {
  float nr0 = fmaf(-s, r1, c * r0), ni0 = fmaf(-s, i1, c * i0);
  float nr1 = fmaf(s, r0, c * r1),  ni1 = fmaf(s, i0, c * i1);
  r0 = nr0; i0 = ni0; r1 = nr1; i1 = ni1;
}

// ---------------------------------------------------------------------------
// Kernel 2: build Ũ per batch
// ---------------------------------------------------------------------------
__global__ __launch_bounds__(256) void k_buildU() {
  int b = blockIdx.x, wid = threadIdx.x >> 5, lane = threadIdx.x & 31;
  const float* cth = g_cth + b * NANG;
  const float* sth = g_sth + b * NANG;
  float* U = g_Uri + b * 8192;
  for (int t = 0; t < 8; t++) {
    int k = wid * 8 + t;
    float r0 = (k < 32 && lane == k) ? 1.f : 0.f;
    float r1 = (k >= 32 && lane == k - 32) ? 1.f : 0.f;
    float i0 = 0.f, i1 = 0.f;
    { float c = cth[0], s = sth[0]; rx_loc(r0, i0, r1, i1, c, s);
      c = cth[1]; s = sth[1]; ry_loc(r0, i0, r1, i1, c, s); }
#pragma unroll
    for (int q = 1; q < 6; q++) {
      int L = 1 << (5 - q);
      float c = cth[q*3+0], s = sth[q*3+0]; rx_sh(r0, i0, r1, i1, c, s, L);
      c = cth[q*3+1]; s = sth[q*3+1]; ry_sh(r0, i0, r1, i1, c, s, L, lane);
    }
    r1 = __shfl_xor_sync(0xffffffffu, r1, 16);
    i1 = __shfl_xor_sync(0xffffffffu, i1, 16);
#pragma unroll
    for (int q = 1; q < 5; q++) {
      int Lc = 1 << (5 - q), Lt = 1 << (4 - q);
      float pr0 = __shfl_xor_sync(0xffffffffu, r0, Lt), pi0 = __shfl_xor_sync(0xffffffffu, i0, Lt);
      float pr1 = __shfl_xor_sync(0xffffffffu, r1, Lt), pi1 = __shfl_xor_sync(0xffffffffu, i1, Lt);
      if (lane & Lc) { r0 = pr0; i0 = pi0; r1 = pr1; i1 = pi1; }
    }
    { float c = cth[2], s = sth[2]; ry_loc(r0, i0, r1, i1, c, s); }
#pragma unroll
    for (int q = 1; q < 6; q++) {
      int L = 1 << (5 - q);
      float c = cth[q*3+2], s = sth[q*3+2]; ry_sh(r0, i0, r1, i1, c, s, L, lane);
    }
    U[(2*lane)*64 + k] = r0;       U[(2*lane+1)*64 + k] = i0;
    U[(2*(lane+32))*64 + k] = r1;  U[(2*(lane+32)+1)*64 + k] = i1;
  }
}

// ---------------------------------------------------------------------------
// Kernel 3: fold W1f = Ũ @ W1 -> fragment-linear fp16 hi/lo + bias fold
// ---------------------------------------------------------------------------
__global__ __launch_bounds__(256) void k_fold(const float* __restrict__ w1,
                                              const float* __restrict__ b1) {
  __shared__ float Us[128 * 64];
  __shared__ float Ws[64 * 64];
  int b = blockIdx.x, ch = blockIdx.y, tid = threadIdx.x;
  const float* Ub = g_Uri + b * 8192;
#pragma unroll
  for (int i = 0; i < 8; i++)
    *(float4*)&Us[(tid + 256 * i) * 4] = *(const float4*)&Ub[(tid + 256 * i) * 4];
#pragma unroll
  for (int i = 0; i < 4; i++) {
    int idx = tid + 256 * i;
    int k = idx >> 4, c4 = (idx & 15) * 4;
    *(float4*)&Ws[k * 64 + c4] = *(const float4*)&w1[k * 256 + 64 * ch + c4];
  }
  __syncthreads();
  int rt = tid >> 4, ct = tid & 15;
  float acc[8][4];
#pragma unroll
  for (int u = 0; u < 8; u++)
#pragma unroll
    for (int v = 0; v < 4; v++) acc[u][v] = 0.f;
#pragma unroll 4
  for (int kk = 0; kk < 64; kk++) {
    float a[8], bb[4];
#pragma unroll
    for (int u = 0; u < 8; u++) a[u] = Us[(8 * rt + u) * 64 + kk];
#pragma unroll
    for (int v = 0; v < 4; v++) bb[v] = Ws[kk * 64 + ct + 16 * v];
#pragma unroll
    for (int u = 0; u < 8; u++)
#pragma unroll
      for (int v = 0; v < 4; v++) acc[u][v] = fmaf(a[u], bb[v], acc[u][v]);
  }
#pragma unroll
  for (int u = 0; u < 8; u++)
#pragma unroll
    for (int v = 0; v < 4; v++) {
      int r = 8 * rt + u, k = 64 * ch + ct + 16 * v;
      ushort_t h, l;
      split16(acc[u][v], h, l);
      int fi = frag_idx(r, k, 16);
      g_A1h[b][fi] = h;
      g_A1l[b][fi] = l;
    }
  if (ch == 0 && tid < 128) {
    float s = 0.f;
#pragma unroll
    for (int k = 0; k < 64; k++) s += Us[tid * 64 + k] * b1[k];
    g_bf[b * 128 + tid] = s;
  }
}

// ---------------------------------------------------------------------------
// Kernel 4: W2 [256c][64k] -> fragment-linear fp16 hi/lo
// ---------------------------------------------------------------------------
__global__ __launch_bounds__(256) void k_w2pack(const float* __restrict__ w2) {
  int idx = blockIdx.x * 256 + threadIdx.x;  // 0..16383
  int c = idx >> 6, k = idx & 63;
  ushort_t h, l;
  split16(w2[idx], h, l);
  int fi = frag_idx(c, k, 4);
  g_A2h[fi] = h;
  g_A2l[fi] = l;
}

// ---------------------------------------------------------------------------
// Kernel 5: fused main (HMMA), conflict-free pitch 136.
// smem (bytes):
//   [0 .. 34816)       XpH [64 kpair][136] u32   } reused as S2 [256][66] f32
//   [34816 .. 69632)   XpL                        }
//   [69632 .. 104448)  Q   [64][136]  (f32 q -> fp16x2 probs hi/lo in place)
//   [104448..104960)   bfs
//   [104960..105984)   b2s
//   [105984..107008)   Ssum (256 f32)
// ---------------------------------------------------------------------------
#define XP      136
#define XPH_OFF 0
#define XPL_OFF 34816
#define Q_OFF   69632
#define BFS_OFF 104448
#define B2S_OFF 104960
#define SSUM_OFF 105984
#define SM_SZ   107008

__global__ __launch_bounds__(256, 2) void k_main(const float* __restrict__ x,
                                                 const float* __restrict__ b2,
                                                 float* __restrict__ out) {
  extern __shared__ unsigned char sm[];
  uint32_t* XpH = (uint32_t*)(sm + XPH_OFF);
  uint32_t* XpL = (uint32_t*)(sm + XPL_OFF);
  float*    S2  = (float*)sm;
  float*    Qf  = (float*)(sm + Q_OFF);
  uint32_t* Qu  = (uint32_t*)(sm + Q_OFF);
  float*    bfs = (float*)(sm + BFS_OFF);
  float*    b2s = (float*)(sm + B2S_OFF);
  float*    Ssum = (float*)(sm + SSUM_OFF);

  int tid = threadIdx.x;
  int w = tid >> 5, lane = tid & 31;
  int gID = lane >> 2, tig = lane & 3;
  int n0 = blockIdx.x * 128;
  int b = n0 >> 12, s0 = n0 & 4095;

  if (tid < 128) bfs[tid] = g_bf[b * 128 + tid];
  b2s[tid] = b2[tid];

  // ================= GEMM1: y = W1f @ x =================
  float C1[16][4];
#pragma unroll
  for (int nt = 0; nt < 16; nt++)
#pragma unroll
    for (int e = 0; e < 4; e++) C1[nt][e] = 0.f;

  const uint4* A1H4 = (const uint4*)g_A1h[b];
  const uint4* A1L4 = (const uint4*)g_A1l[b];

  int kp = tid >> 2, pb = (tid & 3) * 32;

  for (int ck = 0; ck < 2; ck++) {
    // stage x chunk (128 k) as fp16x2 k-pairs, [kpair][pos], pitch XP
    const float* xr0 = x + ((size_t)b * CCH + ck * 128 + 2 * kp) * HW + s0 + pb;
    const float* xr1 = xr0 + HW;
#pragma unroll
    for (int i = 0; i < 8; i++) {
      float4 a = *(const float4*)(xr0 + 4 * i);
      float4 c = *(const float4*)(xr1 + 4 * i);
      float ea[4] = {a.x, a.y, a.z, a.w};
      float ec[4] = {c.x, c.y, c.z, c.w};
      uint32_t hw[4], lw[4];
#pragma unroll
      for (int e = 0; e < 4; e++) {
        __half2 hh = __floats2half2_rn(ea[e], ec[e]);
        hw[e] = *(uint32_t*)&hh;
        float la = ea[e] - __low2float(hh);
        float lc = ec[e] - __high2float(hh);
        __half2 ll = __floats2half2_rn(la, lc);
        lw[e] = *(uint32_t*)&ll;
      }
      *(uint4*)&XpH[kp * XP + pb + 4 * i] = make_uint4(hw[0], hw[1], hw[2], hw[3]);
      *(uint4*)&XpL[kp * XP + pb + 4 * i] = make_uint4(lw[0], lw[1], lw[2], lw[3]);
    }
    __syncthreads();
#pragma unroll
    for (int ksl = 0; ksl < 8; ksl++) {
      int ksg = ck * 8 + ksl;
      uint4 ah = A1H4[(w * 16 + ksg) * 32 + lane];
      uint4 al = A1L4[(w * 16 + ksg) * 32 + lane];
      int r0i = (ksl * 8 + tig) * XP + gID;
      int r1i = (ksl * 8 + 4 + tig) * XP + gID;
#pragma unroll
      for (int nt = 0; nt < 16; nt++) {
        uint32_t bh0 = XpH[r0i + nt * 8], bh1 = XpH[r1i + nt * 8];
        uint32_t bl0 = XpL[r0i + nt * 8], bl1 = XpL[r1i + nt * 8];
        mma16816(C1[nt], ah.x, ah.y, ah.z, ah.w, bh0, bh1);
        mma16816(C1[nt], ah.x, ah.y, ah.z, ah.w, bl0, bl1);
        mma16816(C1[nt], al.x, al.y, al.z, al.w, bh0, bh1);
      }
    }
    __syncthreads();
  }

  // ======== epilogue: bias, square, pair-sum -> Q[j][pos] ========
  {
    float ba = bfs[w * 16 + gID];
    float bbv = bfs[w * 16 + gID + 8];
    int jA = 8 * w + (gID >> 1), jB = jA + 4;
#pragma unroll
    for (int nt = 0; nt < 16; nt++) {
      float y0 = C1[nt][0] + ba, y1 = C1[nt][1] + ba;
      float y2 = C1[nt][2] + bbv, y3 = C1[nt][3] + bbv;
      float q0 = y0 * y0, q1 = y1 * y1, q2 = y2 * y2, q3 = y3 * y3;
      q0 += __shfl_xor_sync(0xffffffffu, q0, 4);
      q1 += __shfl_xor_sync(0xffffffffu, q1, 4);
      q2 += __shfl_xor_sync(0xffffffffu, q2, 4);
      q3 += __shfl_xor_sync(0xffffffffu, q3, 4);
      if (!(gID & 1)) {
        int pos = nt * 8 + tig * 2;
        *(float2*)&Qf[jA * XP + pos] = make_float2(q0, q1);
        *(float2*)&Qf[jB * XP + pos] = make_float2(q2, q3);
      }
    }
  }
  __syncthreads();

  // ======== normalize: 2 threads per position, 32 regs each, alias-safe ====
  {
    int half = tid >> 7, pos = tid & 127;
    float qv[32];
    float S = 0.f;
#pragma unroll
    for (int j = 0; j < 32; j++) {
      qv[j] = Qf[(32 * half + j) * XP + pos];
      S += qv[j];
    }
    Ssum[tid] = S;
    __syncthreads();   // all q reads done before any prob writes below
    float St = Ssum[pos] + Ssum[128 + pos];
    float inv = 1.0f / (sqrtf(St) + 1e-9f);
    float inv2 = inv * inv;
#pragma unroll
    for (int m = 0; m < 16; m++) {
      float p0 = qv[2 * m] * inv2;
      float p1 = qv[2 * m + 1] * inv2;
      __half2 hh = __floats2half2_rn(p0, p1);
      float l0 = p0 - __low2float(hh);
      float l1 = p1 - __high2float(hh);
      __half2 ll = __floats2half2_rn(l0, l1);
      int kpp = 16 * half + m;
      Qu[kpp * XP + pos] = *(uint32_t*)&hh;
      Qu[(32 + kpp) * XP + pos] = *(uint32_t*)&ll;
    }
  }
  __syncthreads();

  // ================= GEMM2: out = W2 @ probs =================
  const uint4* A2H4 = (const uint4*)g_A2h;
  const uint4* A2L4 = (const uint4*)g_A2l;
#pragma unroll 1
  for (int nh = 0; nh < 2; nh++) {
    float C2[2][8][4];
#pragma unroll
    for (int mt = 0; mt < 2; mt++)
#pragma unroll
      for (int nt = 0; nt < 8; nt++)
#pragma unroll
        for (int e = 0; e < 4; e++) C2[mt][nt][e] = 0.f;
#pragma unroll
    for (int ks = 0; ks < 4; ks++) {
      uint4 aH0 = A2H4[((2 * w) * 4 + ks) * 32 + lane];
      uint4 aH1 = A2H4[((2 * w + 1) * 4 + ks) * 32 + lane];
      uint4 aL0 = A2L4[((2 * w) * 4 + ks) * 32 + lane];
      uint4 aL1 = A2L4[((2 * w + 1) * 4 + ks) * 32 + lane];
      int rb0 = (ks * 8 + tig) * XP + nh * 64 + gID;
      int rb1 = (ks * 8 + 4 + tig) * XP + nh * 64 + gID;
#pragma unroll
      for (int nt = 0; nt < 8; nt++) {
        uint32_t bh0 = Qu[rb0 + nt * 8], bh1 = Qu[rb1 + nt * 8];
        uint32_t bl0 = Qu[rb0 + 32 * XP + nt * 8], bl1 = Qu[rb1 + 32 * XP + nt * 8];
        mma16816(C2[0][nt], aH0.x, aH0.y, aH0.z, aH0.w, bh0, bh1);
        mma16816(C2[0][nt], aH0.x, aH0.y, aH0.z, aH0.w, bl0, bl1);
        mma16816(C2[0][nt], aL0.x, aL0.y, aL0.z, aL0.w, bh0, bh1);
        mma16816(C2[1][nt], aH1.x, aH1.y, aH1.z, aH1.w, bh0, bh1);
        mma16816(C2[1][nt], aH1.x, aH1.y, aH1.z, aH1.w, bl0, bl1);
        mma16816(C2[1][nt], aL1.x, aL1.y, aL1.z, aL1.w, bh0, bh1);
      }
    }
    // stage to S2 [256][66]
#pragma unroll
    for (int mt = 0; mt < 2; mt++) {
      int c = w * 32 + mt * 16 + gID;
#pragma unroll
      for (int nt = 0; nt < 8; nt++) {
        int pc = nt * 8 + tig * 2;
        S2[c * 66 + pc]       = C2[mt][nt][0];
        S2[c * 66 + pc + 1]   = C2[mt][nt][1];
        S2[(c + 8) * 66 + pc]     = C2[mt][nt][2];
        S2[(c + 8) * 66 + pc + 1] = C2[mt][nt][3];
      }
    }
    __syncthreads();
    // coalesced store: thread = channel
    {
      float bb2 = b2s[tid];
      float* ob = out + ((size_t)b * CCH + tid) * HW + s0 + nh * 64;
#pragma unroll
      for (int i = 0; i < 16; i++) {
        float2 u = *(float2*)&S2[tid * 66 + 4 * i];
        float2 v = *(float2*)&S2[tid * 66 + 4 * i + 2];
        float4 o = make_float4(u.x + bb2, u.y + bb2, v.x + bb2, v.y + bb2);
        *(float4*)(ob + 4 * i) = o;
      }
    }
    __syncthreads();
  }
}

// ---------------------------------------------------------------------------
extern "C" void kernel_launch(void* const* d_in, const int* in_sizes, int n_in,
                              void* d_out, int out_size) {
  const float* x     = (const float*)d_in[0];
  const float* style = (const float*)d_in[1];
  const float* w1    = (const float*)d_in[2];
  const float* b1    = (const float*)d_in[3];
  const float* smw   = (const float*)d_in[4];
  const float* smb   = (const float*)d_in[5];
  const float* wts   = (const float*)d_in[6];
  const float* w2    = (const float*)d_in[7];
  const float* b2    = (const float*)d_in[8];
  float* out = (float*)d_out;

  cudaFuncSetAttribute(k_main, cudaFuncAttributeMaxDynamicSharedMemorySize, SM_SZ);

  k_angles<<<BATCH, 512>>>(style, smw, smb, wts);
  k_buildU<<<BATCH, 256>>>();
  k_fold<<<dim3(BATCH, 4), 256>>>(w1, b1);
  k_w2pack<<<64, 256>>>(w2);
  k_main<<<NPOS / 128, 256, SM_SZ>>>(x, b2, out);
}

// round 14
// speedup vs baseline: 1.3559x; 1.3559x over previous
#include <cuda_runtime.h>
#include <cuda_fp16.h>
#include <math.h>
#include <stdint.h>

#define BATCH 16
#define CCH   256
#define HW    4096
#define NPOS  (BATCH*HW)
#define QDIM  64
#define SD    512
#define NANG  18

typedef unsigned short ushort_t;

// ---------------- scratch globals ----------------
__device__ float g_bf[BATCH * 128];              // Ũ @ b1
// W1f fragment-linear fp16 hi/lo: per batch 8 mt x 16 ks x 32 lane x 8 ushorts
__device__ __align__(16) ushort_t g_A1h[BATCH][32768];
__device__ __align__(16) ushort_t g_A1l[BATCH][32768];
// W2 fragment-linear: 16 mt x 4 ks x 32 x 8
__device__ __align__(16) ushort_t g_A2h[16384];
__device__ __align__(16) ushort_t g_A2l[16384];

// ---------------- mma helper ----------------
__device__ __forceinline__ void mma16816(float* c, uint32_t a0, uint32_t a1,
                                         uint32_t a2, uint32_t a3,
                                         uint32_t b0, uint32_t b1) {
  asm volatile(
      "mma.sync.aligned.m16n8k16.row.col.f32.f16.f16.f32 "
      "{%0,%1,%2,%3}, {%4,%5,%6,%7}, {%8,%9}, {%0,%1,%2,%3};"
      : "+f"(c[0]), "+f"(c[1]), "+f"(c[2]), "+f"(c[3])
      : "r"(a0), "r"(a1), "r"(a2), "r"(a3), "r"(b0), "r"(b1));
}

__device__ __forceinline__ void split16(float v, ushort_t& h, ushort_t& l) {
  __half hh = __float2half_rn(v);
  float lo = v - __half2float(hh);
  h = __half_as_ushort(hh);
  l = __half_as_ushort(__float2half_rn(lo));
}

// fragment-linear ushort index for A operand (m16n8k16 row-major A)
__device__ __forceinline__ int frag_idx(int r, int k, int KS) {
  int mt = r >> 4, rr = r & 15;
  int gID = rr & 7, sm = rr >> 3;
  int ks = k >> 4, kin = k & 15;
  int sk = kin >> 3, tg = (kin & 7) >> 1, hf = kin & 1;
  return (((mt * KS + ks) * 32 + gID * 4 + tg) * 4 + (sm + 2 * sk)) * 2 + hf;
}

// ---------------- circuit helpers ----------------
__device__ __forceinline__ void rx_sh(float& r0, float& i0, float& r1, float& i1,
                                      float c, float s, int L) {
  float pr0 = __shfl_xor_sync(0xffffffffu, r0, L), pi0 = __shfl_xor_sync(0xffffffffu, i0, L);
  float pr1 = __shfl_xor_sync(0xffffffffu, r1, L), pi1 = __shfl_xor_sync(0xffffffffu, i1, L);
  r0 = fmaf(s, pi0, c * r0);  i0 = fmaf(-s, pr0, c * i0);
  r1 = fmaf(s, pi1, c * r1);  i1 = fmaf(-s, pr1, c * i1);
}
__device__ __forceinline__ void rx_loc(float& r0, float& i0, float& r1, float& i1,
                                       float c, float s) {
  float nr0 = fmaf(s, i1, c * r0), ni0 = fmaf(-s, r1, c * i0);
  float nr1 = fmaf(s, i0, c * r1), ni1 = fmaf(-s, r0, c * i1);
  r0 = nr0; i0 = ni0; r1 = nr1; i1 = ni1;
}
__device__ __forceinline__ void ry_sh(float& r0, float& i0, float& r1, float& i1,
                                      float c, float s, int L, int lane) {
  float t = (lane & L) ? s : -s;
  float pr0 = __shfl_xor_sync(0xffffffffu, r0, L), pi0 = __shfl_xor_sync(0xffffffffu, i0, L);
  float pr1 = __shfl_xor_sync(0xffffffffu, r1, L), pi1 = __shfl_xor_sync(0xffffffffu, i1, L);
  r0 = fmaf(t, pr0, c * r0);  i0 = fmaf(t, pi0, c * i0);
  r1 = fmaf(t, pr1, c * r1);  i1 = fmaf(t, pi1, c * i1);
}
__device__ __forceinline__ void ry_loc(float& r0, float& i0, float& r1, float& i1,
                                       float c, float s) {
  float nr0 = fmaf(-s, r1, c * r0), ni0 = fmaf(-s, i1, c * i0);
  float nr1 = fmaf(s, r0, c * r1),  ni1 = fmaf(s, i0, c * i1);
  r0 = nr0; i0 = ni0; r1 = nr1; i1 = ni1;
}

// ---------------------------------------------------------------------------
// Kernel 1 (single prep kernel, 68 blocks x 256 threads):
//   blocks 0..63 : b = blk>>2, ch = blk&3. Compute angles + U (redundantly per
//                  block; cheap) in smem, then fold W1f col-tile ch -> frag
//                  images. Block with ch==0 also folds the bias.
//   blocks 64..67: W2 -> fragment images.
// ---------------------------------------------------------------------------
#define PREP_US  0        // 32768 B : Us[128*64]
#define PREP_WS  32768    // 16384 B : Ws[64*64]
#define PREP_ANG 49152    // cth[18], sth[18]
#define PREP_SZ  (49152 + 160)

__global__ __launch_bounds__(256) void k_prep(
    const float* __restrict__ style, const float* __restrict__ smw,
    const float* __restrict__ smb, const float* __restrict__ wts,
    const float* __restrict__ w1, const float* __restrict__ b1,
    const float* __restrict__ w2) {
  int blk = blockIdx.x;
  int tid = threadIdx.x;
  if (blk >= 64) {
    // ---- W2 pack ----
    int base = (blk - 64) * 4096 + tid;
#pragma unroll
    for (int i = 0; i < 16; i++) {
      int idx = base + 256 * i;
      int c = idx >> 6, k = idx & 63;
      ushort_t h, l;
      split16(w2[idx], h, l);
      int fi = frag_idx(c, k, 4);
      g_A2h[fi] = h;
      g_A2l[fi] = l;
    }
    return;
  }
  extern __shared__ unsigned char pm[];
  float* Us  = (float*)(pm + PREP_US);
  float* Ws  = (float*)(pm + PREP_WS);
  float* cth = (float*)(pm + PREP_ANG);
  float* sth = cth + NANG;

  int b = blk >> 2, ch = blk & 3;
  int w = tid >> 5, lane = tid & 31;

  // ---- angles: warp-per-output dot products ----
  for (int o = w; o < NANG; o += 8) {
    float p = 0.f;
#pragma unroll
    for (int j = 0; j < 16; j++)
      p += smw[o * SD + lane + 32 * j] * style[b * SD + lane + 32 * j];
#pragma unroll
    for (int off = 16; off > 0; off >>= 1) p += __shfl_xor_sync(0xffffffffu, p, off);
    if (lane == 0) {
      float tp = wts[o] + smb[o] + p;
      cth[o] = cosf(0.5f * tp);
      sth[o] = sinf(0.5f * tp);
    }
  }
  __syncthreads();

  // ---- build U into smem (8 warps x 8 basis vectors) ----
  for (int t = 0; t < 8; t++) {
    int k = w * 8 + t;
    float r0 = (k < 32 && lane == k) ? 1.f : 0.f;
    float r1 = (k >= 32 && lane == k - 32) ? 1.f : 0.f;
    float i0 = 0.f, i1 = 0.f;
    { float c = cth[0], s = sth[0]; rx_loc(r0, i0, r1, i1, c, s);
      c = cth[1]; s = sth[1]; ry_loc(r0, i0, r1, i1, c, s); }
#pragma unroll
    for (int q = 1; q < 6; q++) {
      int L = 1 << (5 - q);
      float c = cth[q*3+0], s = sth[q*3+0]; rx_sh(r0, i0, r1, i1, c, s, L);
      c = cth[q*3+1]; s = sth[q*3+1]; ry_sh(r0, i0, r1, i1, c, s, L, lane);
    }
    r1 = __shfl_xor_sync(0xffffffffu, r1, 16);
    i1 = __shfl_xor_sync(0xffffffffu, i1, 16);
#pragma unroll
    for (int q = 1; q < 5; q++) {
      int Lc = 1 << (5 - q), Lt = 1 << (4 - q);
      float pr0 = __shfl_xor_sync(0xffffffffu, r0, Lt), pi0 = __shfl_xor_sync(0xffffffffu, i0, Lt);
      float pr1 = __shfl_xor_sync(0xffffffffu, r1, Lt), pi1 = __shfl_xor_sync(0xffffffffu, i1, Lt);
      if (lane & Lc) { r0 = pr0; i0 = pi0; r1 = pr1; i1 = pi1; }
    }
    { float c = cth[2], s = sth[2]; ry_loc(r0, i0, r1, i1, c, s); }
#pragma unroll
    for (int q = 1; q < 6; q++) {
      int L = 1 << (5 - q);
      float c = cth[q*3+2], s = sth[q*3+2]; ry_sh(r0, i0, r1, i1, c, s, L, lane);
    }
    Us[(2*lane)*64 + k] = r0;       Us[(2*lane+1)*64 + k] = i0;
    Us[(2*(lane+32))*64 + k] = r1;  Us[(2*(lane+32)+1)*64 + k] = i1;
  }

  // ---- load W1 col-tile ----
#pragma unroll
  for (int i = 0; i < 4; i++) {
    int idx = tid + 256 * i;
    int k = idx >> 4, c4 = (idx & 15) * 4;
    *(float4*)&Ws[k * 64 + c4] = *(const float4*)&w1[k * 256 + 64 * ch + c4];
  }
  __syncthreads();

  // ---- fold W1f = Ũ @ W1 tile -> frag images ----
  int rt = tid >> 4, ct = tid & 15;
  float acc[8][4];
#pragma unroll
  for (int u = 0; u < 8; u++)
#pragma unroll
    for (int v = 0; v < 4; v++) acc[u][v] = 0.f;
#pragma unroll 4
  for (int kk = 0; kk < 64; kk++) {
    float a[8], bb[4];
#pragma unroll
    for (int u = 0; u < 8; u++) a[u] = Us[(8 * rt + u) * 64 + kk];
#pragma unroll
    for (int v = 0; v < 4; v++) bb[v] = Ws[kk * 64 + ct + 16 * v];
#pragma unroll
    for (int u = 0; u < 8; u++)
#pragma unroll
      for (int v = 0; v < 4; v++) acc[u][v] = fmaf(a[u], bb[v], acc[u][v]);
  }
#pragma unroll
  for (int u = 0; u < 8; u++)
#pragma unroll
    for (int v = 0; v < 4; v++) {
      int r = 8 * rt + u, kcol = 64 * ch + ct + 16 * v;
      ushort_t h, l;
      split16(acc[u][v], h, l);
      int fi = frag_idx(r, kcol, 16);
      g_A1h[b][fi] = h;
      g_A1l[b][fi] = l;
    }
  if (ch == 0 && tid < 128) {
    float s = 0.f;
#pragma unroll
    for (int k = 0; k < 64; k++) s += Us[tid * 64 + k] * b1[k];
    g_bf[b * 128 + tid] = s;
  }
}

// ---------------------------------------------------------------------------
// Kernel 2: fused main (HMMA), conflict-free pitch 136, coalesced staging.
// smem (bytes):
//   [0 .. 34816)       XpH [64 kpair][136] u32   } reused as S2 [256][66] f32
//   [34816 .. 69632)   XpL                        }
//   [69632 .. 104448)  Q   [64][136]  (f32 q -> fp16x2 probs hi/lo in place)
//   [104448..104960)   bfs
//   [104960..105984)   b2s
//   [105984..107008)   Ssum (256 f32)
// ---------------------------------------------------------------------------
#define XP      136
#define XPH_OFF 0
#define XPL_OFF 34816
#define Q_OFF   69632
#define BFS_OFF 104448
#define B2S_OFF 104960
#define SSUM_OFF 105984
#define SM_SZ   107008

__global__ __launch_bounds__(256, 2) void k_main(const float* __restrict__ x,
                                                 const float* __restrict__ b2,
                                                 float* __restrict__ out) {
  extern __shared__ unsigned char sm[];
  uint32_t* XpH = (uint32_t*)(sm + XPH_OFF);
  uint32_t* XpL = (uint32_t*)(sm + XPL_OFF);
  float*    S2  = (float*)sm;
  float*    Qf  = (float*)(sm + Q_OFF);
  uint32_t* Qu  = (uint32_t*)(sm + Q_OFF);
  float*    bfs = (float*)(sm + BFS_OFF);
  float*    b2s = (float*)(sm + B2S_OFF);
  float*    Ssum = (float*)(sm + SSUM_OFF);

  int tid = threadIdx.x;
  int w = tid >> 5, lane = tid & 31;
  int gID = lane >> 2, tig = lane & 3;
  int n0 = blockIdx.x * 128;
  int b = n0 >> 12, s0 = n0 & 4095;

  if (tid < 128) bfs[tid] = g_bf[b * 128 + tid];
  b2s[tid] = b2[tid];

  // ================= GEMM1: y = W1f @ x =================
  float C1[16][4];
#pragma unroll
  for (int nt = 0; nt < 16; nt++)
#pragma unroll
    for (int e = 0; e < 4; e++) C1[nt][e] = 0.f;

  const uint4* A1H4 = (const uint4*)g_A1h[b];
  const uint4* A1L4 = (const uint4*)g_A1l[b];

  int kq = tid >> 6;          // 0..3
  int p2 = (tid & 63) * 2;    // even position

  for (int ck = 0; ck < 2; ck++) {
    // stage x chunk (128 k) as fp16x2 k-pairs [kpair][pos]; fully coalesced:
    // warp lanes cover 64 consecutive floats (2 per lane) of one row.
    const float* xc = x + ((size_t)b * CCH + ck * 128) * HW + s0 + p2;
#pragma unroll
    for (int it = 0; it < 16; it++) {
      int kp = it * 4 + kq;   // 0..63
      float2 ev = *(const float2*)(xc + (size_t)(2 * kp) * HW);
      float2 ov = *(const float2*)(xc + (size_t)(2 * kp + 1) * HW);
      __half2 h0 = __floats2half2_rn(ev.x, ov.x);
      __half2 h1 = __floats2half2_rn(ev.y, ov.y);
      float l0a = ev.x - __low2float(h0), l0b = ov.x - __high2float(h0);
      float l1a = ev.y - __low2float(h1), l1b = ov.y - __high2float(h1);
      __half2 g0 = __floats2half2_rn(l0a, l0b);
      __half2 g1 = __floats2half2_rn(l1a, l1b);
      *(uint2*)&XpH[kp * XP + p2] = make_uint2(*(uint32_t*)&h0, *(uint32_t*)&h1);
      *(uint2*)&XpL[kp * XP + p2] = make_uint2(*(uint32_t*)&g0, *(uint32_t*)&g1);
    }
    __syncthreads();
#pragma unroll
    for (int ksl = 0; ksl < 8; ksl++) {
      int ksg = ck * 8 + ksl;
      uint4 ah = A1H4[(w * 16 + ksg) * 32 + lane];
      uint4 al = A1L4[(w * 16 + ksg) * 32 + lane];
      int r0i = (ksl * 8 + tig) * XP + gID;
      int r1i = (ksl * 8 + 4 + tig) * XP + gID;
#pragma unroll
      for (int nt = 0; nt < 16; nt++) {
        uint32_t bh0 = XpH[r0i + nt * 8], bh1 = XpH[r1i + nt * 8];
        uint32_t bl0 = XpL[r0i + nt * 8], bl1 = XpL[r1i + nt * 8];
        mma16816(C1[nt], ah.x, ah.y, ah.z, ah.w, bh0, bh1);
        mma16816(C1[nt], ah.x, ah.y, ah.z, ah.w, bl0, bl1);
        mma16816(C1[nt], al.x, al.y, al.z, al.w, bh0, bh1);
      }
    }
    __syncthreads();
  }

  // ======== epilogue: bias, square, pair-sum -> Q[j][pos] ========
  {
    float ba = bfs[w * 16 + gID];
    float bbv = bfs[w * 16 + gID + 8];
    int jA = 8 * w + (gID >> 1), jB = jA + 4;
#pragma unroll
    for (int nt = 0; nt < 16; nt++) {
      float y0 = C1[nt][0] + ba, y1 = C1[nt][1] + ba;
      float y2 = C1[nt][2] + bbv, y3 = C1[nt][3] + bbv;
      float q0 = y0 * y0, q1 = y1 * y1, q2 = y2 * y2, q3 = y3 * y3;
      q0 += __shfl_xor_sync(0xffffffffu, q0, 4);
      q1 += __shfl_xor_sync(0xffffffffu, q1, 4);
      q2 += __shfl_xor_sync(0xffffffffu, q2, 4);
      q3 += __shfl_xor_sync(0xffffffffu, q3, 4);
      if (!(gID & 1)) {
        int pos = nt * 8 + tig * 2;
        *(float2*)&Qf[jA * XP + pos] = make_float2(q0, q1);
        *(float2*)&Qf[jB * XP + pos] = make_float2(q2, q3);
      }
    }
  }
  __syncthreads();

  // ======== normalize: 2 threads per position, 32 regs each, alias-safe ====
  {
    int half = tid >> 7, pos = tid & 127;
    float qv[32];
    float S = 0.f;
#pragma unroll
    for (int j = 0; j < 32; j++) {
      qv[j] = Qf[(32 * half + j) * XP + pos];
      S += qv[j];
    }
    Ssum[tid] = S;
    __syncthreads();   // all q reads done before any prob writes below
    float St = Ssum[pos] + Ssum[128 + pos];
    float inv = 1.0f / (sqrtf(St) + 1e-9f);
    float inv2 = inv * inv;
#pragma unroll
    for (int m = 0; m < 16; m++) {
      float p0 = qv[2 * m] * inv2;
      float p1 = qv[2 * m + 1] * inv2;
      __half2 hh = __floats2half2_rn(p0, p1);
      float l0 = p0 - __low2float(hh);
      float l1 = p1 - __high2float(hh);
      __half2 ll = __floats2half2_rn(l0, l1);
      int kpp = 16 * half + m;
      Qu[kpp * XP + pos] = *(uint32_t*)&hh;
      Qu[(32 + kpp) * XP + pos] = *(uint32_t*)&ll;
    }
  }
  __syncthreads();

  // ================= GEMM2: out = W2 @ probs =================
  const uint4* A2H4 = (const uint4*)g_A2h;
  const uint4* A2L4 = (const uint4*)g_A2l;
#pragma unroll 1
  for (int nh = 0; nh < 2; nh++) {
    float C2[2][8][4];
#pragma unroll
    for (int mt = 0; mt < 2; mt++)
#pragma unroll
      for (int nt = 0; nt < 8; nt++)
#pragma unroll
        for (int e = 0; e < 4; e++) C2[mt][nt][e] = 0.f;
#pragma unroll
    for (int ks = 0; ks < 4; ks++) {
      uint4 aH0 = A2H4[((2 * w) * 4 + ks) * 32 + lane];
      uint4 aH1 = A2H4[((2 * w + 1) * 4 + ks) * 32 + lane];
      uint4 aL0 = A2L4[((2 * w) * 4 + ks) * 32 + lane];
      uint4 aL1 = A2L4[((2 * w + 1) * 4 + ks) * 32 + lane];
      int rb0 = (ks * 8 + tig) * XP + nh * 64 + gID;
      int rb1 = (ks * 8 + 4 + tig) * XP + nh * 64 + gID;
#pragma unroll
      for (int nt = 0; nt < 8; nt++) {
        uint32_t bh0 = Qu[rb0 + nt * 8], bh1 = Qu[rb1 + nt * 8];
        uint32_t bl0 = Qu[rb0 + 32 * XP + nt * 8], bl1 = Qu[rb1 + 32 * XP + nt * 8];
        mma16816(C2[0][nt], aH0.x, aH0.y, aH0.z, aH0.w, bh0, bh1);
        mma16816(C2[0][nt], aH0.x, aH0.y, aH0.z, aH0.w, bl0, bl1);
        mma16816(C2[0][nt], aL0.x, aL0.y, aL0.z, aL0.w, bh0, bh1);
        mma16816(C2[1][nt], aH1.x, aH1.y, aH1.z, aH1.w, bh0, bh1);
        mma16816(C2[1][nt], aH1.x, aH1.y, aH1.z, aH1.w, bl0, bl1);
        mma16816(C2[1][nt], aL1.x, aL1.y, aL1.z, aL1.w, bh0, bh1);
      }
    }
    // stage to S2 [256][66]
#pragma unroll
    for (int mt = 0; mt < 2; mt++) {
      int c = w * 32 + mt * 16 + gID;
#pragma unroll
      for (int nt = 0; nt < 8; nt++) {
        int pc = nt * 8 + tig * 2;
        S2[c * 66 + pc]       = C2[mt][nt][0];
        S2[c * 66 + pc + 1]   = C2[mt][nt][1];
        S2[(c + 8) * 66 + pc]     = C2[mt][nt][2];
        S2[(c + 8) * 66 + pc + 1] = C2[mt][nt][3];
      }
    }
    __syncthreads();
    // coalesced store: thread = channel
    {
      float bb2 = b2s[tid];
      float* ob = out + ((size_t)b * CCH + tid) * HW + s0 + nh * 64;
#pragma unroll
      for (int i = 0; i < 16; i++) {
        float2 u = *(float2*)&S2[tid * 66 + 4 * i];
        float2 v = *(float2*)&S2[tid * 66 + 4 * i + 2];
        float4 o = make_float4(u.x + bb2, u.y + bb2, v.x + bb2, v.y + bb2);
        *(float4*)(ob + 4 * i) = o;
      }
    }
    __syncthreads();
  }
}

// ---------------------------------------------------------------------------
extern "C" void kernel_launch(void* const* d_in, const int* in_sizes, int n_in,
                              void* d_out, int out_size) {
  const float* x     = (const float*)d_in[0];
  const float* style = (const float*)d_in[1];
  const float* w1    = (const float*)d_in[2];
  const float* b1    = (const float*)d_in[3];
  const float* smw   = (const float*)d_in[4];
  const float* smb   = (const float*)d_in[5];
  const float* wts   = (const float*)d_in[6];
  const float* w2    = (const float*)d_in[7];
  const float* b2    = (const float*)d_in[8];
  float* out = (float*)d_out;

  cudaFuncSetAttribute(k_prep, cudaFuncAttributeMaxDynamicSharedMemorySize, PREP_SZ);
  cudaFuncSetAttribute(k_main, cudaFuncAttributeMaxDynamicSharedMemorySize, SM_SZ);

  k_prep<<<68, 256, PREP_SZ>>>(style, smw, smb, wts, w1, b1, w2);
  k_main<<<NPOS / 128, 256, SM_SZ>>>(x, b2, out);
}